// round 16
// baseline (speedup 1.0000x reference)
#include <cuda_runtime.h>
#include <cuda_fp16.h>
#include <math.h>

// ---------------- problem constants ----------------
#define NN     50000
#define EE     800000
#define ET     850000      // EE + NN self loops
#define INCH   128
#define H1     4
#define C1     64
#define F1     256         // H1*C1
#define C2     64
#define CAP    64          // bucket capacity per node (P(deg+1 > 64) ~ 1e-20)

#define GEMM1_MBLK  ((NN + 127) / 128)       // 391
#define GEMM1_BLOCKS (GEMM1_MBLK * 2)        // 782 (2 head-pairs)
#define BUCKET_BLOCKS 832

// ---------------- device scratch ----------------
__device__ __half g_h1h[NN * F1];     // x @ W1 (fp16)
__device__ __half g_o1h[NN * F1];     // elu(layer1 out + b1) fp16 (GEMM2 input)
__device__ __half g_h2h[NN * C2];     // o1 @ W2 (fp16)
__device__ float  g_es1[NN * H1];
__device__ float  g_ed1[NN * H1];
__device__ float  g_es2[NN];
__device__ float  g_ed2[NN];
__device__ int    g_wp[NN];           // per-node incoming count (zeroed at start, re-zeroed at end)
__device__ int    g_src[NN * CAP];    // bucketed source nodes per dst

// ---------------- helpers ----------------
__device__ __forceinline__ float elu(float x) {
    return x > 0.f ? x : (expf(x) - 1.f);
}
__device__ __forceinline__ float lrelu(float x) {
    return fmaxf(x, 0.2f * x);
}
// fp16 m16n8k16 MMA, fp32 accumulate
__device__ __forceinline__ void mma_f16(float* d, const unsigned* a, const unsigned* b) {
    asm volatile(
        "mma.sync.aligned.m16n8k16.row.col.f32.f16.f16.f32 "
        "{%0,%1,%2,%3}, {%4,%5,%6,%7}, {%8,%9}, {%0,%1,%2,%3};"
        : "+f"(d[0]), "+f"(d[1]), "+f"(d[2]), "+f"(d[3])
        : "r"(a[0]), "r"(a[1]), "r"(a[2]), "r"(a[3]), "r"(b[0]), "r"(b[1]));
}

// ================= GEMM1 wide body: 128(M) x 128(N = 2 heads), fp16 split-A =================
// Double-buffered smem stages: 1 syncthreads per stage, STS(s+1) overlaps MMA(s).
__device__ void gemm1_body(
        const float* __restrict__ A, const float* __restrict__ B,
        const float* __restrict__ asrc, const float* __restrict__ adst,
        __half* __restrict__ hout,
        float* __restrict__ es, float* __restrict__ ed,
        int headpair, int by) {
    __shared__ unsigned Ash[2][2][128][12];   // [buf][hi/lo][m][kpair]
    __shared__ unsigned Bsh[2][8][136];       // [buf][kpair][n]
    __shared__ float s_as[128], s_ad[128];

    const int M = NN, N = F1, K = INCH, H = H1;
    int tid = threadIdx.x;
    int lane = tid & 31, wid = tid >> 5;
    int warp_m = wid >> 1, warp_n = wid & 1;
    int g = lane >> 2, t = lane & 3;
    int bm0 = by * 128, bn0 = headpair * 128;
    int head = headpair * 2 + warp_n;

    if (tid < 128) {
        s_as[tid] = asrc[bn0 + tid];
        s_ad[tid] = adst[bn0 + tid];
    }

    float acc[2][8][4];
    #pragma unroll
    for (int im = 0; im < 2; im++)
        #pragma unroll
        for (int in = 0; in < 8; in++)
            #pragma unroll
            for (int c = 0; c < 4; c++) acc[im][in][c] = 0.f;

    int arow = tid >> 1;
    int acb  = (tid & 1) * 8;
    int apb  = (tid & 1) * 4;
    bool arow_ok = (bm0 + arow) < M;
    const float* aptrf = A + (size_t)(bm0 + arow) * K + acb;
    int brp = tid >> 5;
    int bnc = lane * 4;
    const float* bptr = B + (size_t)(2 * brp) * N + bn0 + bnc;

    float4 av0 = make_float4(0,0,0,0), av1 = av0, bve, bvo;
    if (arow_ok) {
        av0 = *reinterpret_cast<const float4*>(aptrf);
        av1 = *reinterpret_cast<const float4*>(aptrf + 4);
    }
    bve = *reinterpret_cast<const float4*>(bptr);
    bvo = *reinterpret_cast<const float4*>(bptr + N);

    auto stage_sts = [&](int buf) {
        float vv[8] = {av0.x, av0.y, av0.z, av0.w, av1.x, av1.y, av1.z, av1.w};
        __half h[8], l[8];
        #pragma unroll
        for (int j = 0; j < 8; j++) {
            h[j] = __float2half_rn(vv[j]);
            l[j] = __float2half_rn(vv[j] - __half2float(h[j]));
        }
        unsigned ph[4], pl[4];
        #pragma unroll
        for (int p = 0; p < 4; p++) {
            __half2 hh = __halves2half2(h[2*p], h[2*p+1]);
            __half2 ll = __halves2half2(l[2*p], l[2*p+1]);
            ph[p] = *reinterpret_cast<unsigned*>(&hh);
            pl[p] = *reinterpret_cast<unsigned*>(&ll);
        }
        *reinterpret_cast<uint4*>(&Ash[buf][0][arow][apb]) = make_uint4(ph[0],ph[1],ph[2],ph[3]);
        *reinterpret_cast<uint4*>(&Ash[buf][1][arow][apb]) = make_uint4(pl[0],pl[1],pl[2],pl[3]);

        __half2 p0 = __halves2half2(__float2half_rn(bve.x), __float2half_rn(bvo.x));
        __half2 p1 = __halves2half2(__float2half_rn(bve.y), __float2half_rn(bvo.y));
        __half2 p2 = __halves2half2(__float2half_rn(bve.z), __float2half_rn(bvo.z));
        __half2 p3 = __halves2half2(__float2half_rn(bve.w), __float2half_rn(bvo.w));
        *reinterpret_cast<uint4*>(&Bsh[buf][brp][bnc]) = make_uint4(
            *reinterpret_cast<unsigned*>(&p0), *reinterpret_cast<unsigned*>(&p1),
            *reinterpret_cast<unsigned*>(&p2), *reinterpret_cast<unsigned*>(&p3));
    };

    stage_sts(0);
    __syncthreads();

    const int S = K / 16;   // 8 stages
    for (int s = 0; s < S; s++) {
        int buf = s & 1;
        int kn = (s + 1) * 16;
        if (kn < K) {
            if (arow_ok) {
                av0 = *reinterpret_cast<const float4*>(aptrf + kn);
                av1 = *reinterpret_cast<const float4*>(aptrf + kn + 4);
            }
            bve = *reinterpret_cast<const float4*>(bptr + (size_t)kn * N);
            bvo = *reinterpret_cast<const float4*>(bptr + (size_t)(kn + 1) * N);
        }

        {
            unsigned ah[2][4], al[2][4], bf[8][2];
            #pragma unroll
            for (int im = 0; im < 2; im++) {
                int mr = warp_m * 32 + im * 16 + g;
                ah[im][0] = Ash[buf][0][mr][t];
                ah[im][1] = Ash[buf][0][mr + 8][t];
                ah[im][2] = Ash[buf][0][mr][t + 4];
                ah[im][3] = Ash[buf][0][mr + 8][t + 4];
                al[im][0] = Ash[buf][1][mr][t];
                al[im][1] = Ash[buf][1][mr + 8][t];
                al[im][2] = Ash[buf][1][mr][t + 4];
                al[im][3] = Ash[buf][1][mr + 8][t + 4];
            }
            #pragma unroll
            for (int in = 0; in < 8; in++) {
                int nc = warp_n * 64 + in * 8 + g;
                bf[in][0] = Bsh[buf][t][nc];
                bf[in][1] = Bsh[buf][t + 4][nc];
            }
            #pragma unroll
            for (int im = 0; im < 2; im++)
                #pragma unroll
                for (int in = 0; in < 8; in++) {
                    mma_f16(acc[im][in], ah[im], bf[in]);
                    mma_f16(acc[im][in], al[im], bf[in]);
                }
        }

        if (kn < K) stage_sts(buf ^ 1);
        __syncthreads();
    }

    #pragma unroll
    for (int im = 0; im < 2; im++) {
        #pragma unroll
        for (int hh = 0; hh < 2; hh++) {
            int row = bm0 + warp_m * 32 + im * 16 + hh * 8 + g;
            float pe = 0.f, pd = 0.f;
            #pragma unroll
            for (int in = 0; in < 8; in++) {
                int c = warp_n * 64 + in * 8 + 2 * t;
                float v0 = acc[im][in][2 * hh];
                float v1 = acc[im][in][2 * hh + 1];
                pe += v0 * s_as[c] + v1 * s_as[c + 1];
                pd += v0 * s_ad[c] + v1 * s_ad[c + 1];
                if (row < M) {
                    __half2 p = __floats2half2_rn(v0, v1);
                    *reinterpret_cast<__half2*>(&hout[(size_t)row * N + bn0 + c]) = p;
                }
            }
            pe += __shfl_down_sync(0xffffffffu, pe, 1, 4);
            pe += __shfl_down_sync(0xffffffffu, pe, 2, 4);
            pd += __shfl_down_sync(0xffffffffu, pd, 1, 4);
            pd += __shfl_down_sync(0xffffffffu, pd, 2, 4);
            if (t == 0 && row < M) {
                es[row * H + head] = pe;
                ed[row * H + head] = pd;
            }
        }
    }
}

// ================= GEMM2 body: 128(M) x 64(N), fp16 A, prefetch =================
#define BKT 16
__device__ void gemm2_body(
        const __half* __restrict__ A, const float* __restrict__ B,
        const float* __restrict__ asrc, const float* __restrict__ adst,
        __half* __restrict__ hout,
        float* __restrict__ es, float* __restrict__ ed,
        int by) {
    const int M = NN, N = C2, K = F1;
    __shared__ unsigned Ash[128][12];
    __shared__ unsigned Bsh[8][72];
    __shared__ float s_as[64], s_ad[64];
    __shared__ float s_esp[2][128], s_edp[2][128];

    int tid = threadIdx.x;
    int lane = tid & 31, wid = tid >> 5;
    int warp_m = wid >> 1, warp_n = wid & 1;
    int g = lane >> 2, t = lane & 3;
    int bm0 = by * 128;

    if (tid < 64) {
        s_as[tid] = asrc[tid];
        s_ad[tid] = adst[tid];
    }

    float acc[2][4][4];
    #pragma unroll
    for (int im = 0; im < 2; im++)
        #pragma unroll
        for (int in = 0; in < 4; in++)
            #pragma unroll
            for (int c = 0; c < 4; c++) acc[im][in][c] = 0.f;

    int arow = tid >> 1;
    int acb  = (tid & 1) * 8;
    int apb  = (tid & 1) * 4;
    bool arow_ok = (bm0 + arow) < M;
    const __half* aptrh = A + (size_t)(bm0 + arow) * K + acb;
    int brp = tid >> 4;
    int bnc = (tid & 15) * 4;
    const float* bptr = B + (size_t)(2 * brp) * N + bnc;
    bool bload = tid < 128;

    uint4 ar = make_uint4(0u,0u,0u,0u);
    float4 bve = make_float4(0,0,0,0), bvo = bve;
    if (arow_ok) ar = *reinterpret_cast<const uint4*>(aptrh);
    if (bload) {
        bve = *reinterpret_cast<const float4*>(bptr);
        bvo = *reinterpret_cast<const float4*>(bptr + N);
    }

    for (int k0 = 0; k0 < K; k0 += BKT) {
        *reinterpret_cast<uint4*>(&Ash[arow][apb]) = ar;
        if (bload) {
            __half2 p0 = __halves2half2(__float2half_rn(bve.x), __float2half_rn(bvo.x));
            __half2 p1 = __halves2half2(__float2half_rn(bve.y), __float2half_rn(bvo.y));
            __half2 p2 = __halves2half2(__float2half_rn(bve.z), __float2half_rn(bvo.z));
            __half2 p3 = __halves2half2(__float2half_rn(bve.w), __float2half_rn(bvo.w));
            *reinterpret_cast<uint4*>(&Bsh[brp][bnc]) = make_uint4(
                *reinterpret_cast<unsigned*>(&p0), *reinterpret_cast<unsigned*>(&p1),
                *reinterpret_cast<unsigned*>(&p2), *reinterpret_cast<unsigned*>(&p3));
        }
        __syncthreads();

        int kn = k0 + BKT;
        if (kn < K) {
            if (arow_ok) ar = *reinterpret_cast<const uint4*>(aptrh + kn);
            if (bload) {
                bve = *reinterpret_cast<const float4*>(bptr + (size_t)kn * N);
                bvo = *reinterpret_cast<const float4*>(bptr + (size_t)(kn + 1) * N);
            }
        }

        {
            unsigned ah[2][4], bf[4][2];
            #pragma unroll
            for (int im = 0; im < 2; im++) {
                int mr = warp_m * 32 + im * 16 + g;
                ah[im][0] = Ash[mr][t];
                ah[im][1] = Ash[mr + 8][t];
                ah[im][2] = Ash[mr][t + 4];
                ah[im][3] = Ash[mr + 8][t + 4];
            }
            #pragma unroll
            for (int in = 0; in < 4; in++) {
                int nc = warp_n * 32 + in * 8 + g;
                bf[in][0] = Bsh[t][nc];
                bf[in][1] = Bsh[t + 4][nc];
            }
            #pragma unroll
            for (int im = 0; im < 2; im++)
                #pragma unroll
                for (int in = 0; in < 4; in++)
                    mma_f16(acc[im][in], ah[im], bf[in]);
        }
        __syncthreads();
    }

    #pragma unroll
    for (int im = 0; im < 2; im++) {
        #pragma unroll
        for (int hh = 0; hh < 2; hh++) {
            int lr = warp_m * 32 + im * 16 + hh * 8 + g;
            int row = bm0 + lr;
            float pe = 0.f, pd = 0.f;
            #pragma unroll
            for (int in = 0; in < 4; in++) {
                int c = warp_n * 32 + in * 8 + 2 * t;
                float v0 = acc[im][in][2 * hh];
                float v1 = acc[im][in][2 * hh + 1];
                pe += v0 * s_as[c] + v1 * s_as[c + 1];
                pd += v0 * s_ad[c] + v1 * s_ad[c + 1];
                if (row < M) {
                    __half2 p = __floats2half2_rn(v0, v1);
                    *reinterpret_cast<__half2*>(&hout[(size_t)row * N + c]) = p;
                }
            }
            pe += __shfl_down_sync(0xffffffffu, pe, 1, 4);
            pe += __shfl_down_sync(0xffffffffu, pe, 2, 4);
            pd += __shfl_down_sync(0xffffffffu, pd, 1, 4);
            pd += __shfl_down_sync(0xffffffffu, pd, 2, 4);
            if (t == 0) {
                s_esp[warp_n][lr] = pe;
                s_edp[warp_n][lr] = pd;
            }
        }
    }
    __syncthreads();
    if (tid < 128) {
        int row = bm0 + tid;
        if (row < M) {
            es[row] = s_esp[0][tid] + s_esp[1][tid];
            ed[row] = s_edp[0][tid] + s_edp[1][tid];
        }
    }
}

// ---------------- combined kernel: edge-bucket blocks FIRST, then GEMM1 blocks ----------------
__global__ __launch_bounds__(256) void gemm1_plus_bucket(
        const float* __restrict__ A, const float* __restrict__ B,
        const float* __restrict__ asrc, const float* __restrict__ adst,
        __half* __restrict__ hout,
        float* __restrict__ es, float* __restrict__ ed,
        const int* __restrict__ edge_index) {
    int bx = blockIdx.x;
    if (bx < BUCKET_BLOCKS) {
        const int* srcp = edge_index;
        const int* dstp = edge_index + EE;
        int i = bx * 256 + threadIdx.x;
        int stride = BUCKET_BLOCKS * 256;
        for (int e = i; e < ET; e += stride) {
            int s, d;
            if (e < EE) { s = srcp[e]; d = dstp[e]; }
            else { s = e - EE; d = s; }
            int slot = atomicAdd(&g_wp[d], 1);
            g_src[d * CAP + slot] = s;
        }
    } else {
        int gb = bx - BUCKET_BLOCKS;
        gemm1_body(A, B, asrc, adst, hout, es, ed, gb & 1, gb >> 1);
    }
}

// ---------------- GEMM2 kernel ----------------
__global__ __launch_bounds__(256) void gemm2_kernel(
        const __half* __restrict__ A, const float* __restrict__ B,
        const float* __restrict__ asrc, const float* __restrict__ adst,
        __half* __restrict__ hout,
        float* __restrict__ es, float* __restrict__ ed) {
    gemm2_body(A, B, asrc, adst, hout, es, ed, blockIdx.x);
}

// ---------------- layer-1 aggregation: 2 warps/node, edge-interleaved ----------------
// Block = 8 warps = 4 nodes x 2 warps. Phase A: one bucket slot per lane (CAP=64),
// zero duplication; partial sums combined via smem + block sync. Phase B: warp h
// takes edges h, h+2, ... at full 512B width; accumulators combined via smem.
__global__ __launch_bounds__(256) void agg1_fused(
        const float* __restrict__ es,
        const float* __restrict__ ed,
        const float* __restrict__ b1) {
    __shared__ float s_p[4][64][H1];    // unnormalized p
    __shared__ int   s_sn[4][64];
    __shared__ float s_sum[4][2][H1];
    __shared__ float s_acc[4][8][32];   // warp1 partial accum: [nl][j][lane] = ch lane*8+j
    int tid = threadIdx.x;
    int wid = tid >> 5, lane = tid & 31;
    int nl = wid >> 1, half = wid & 1;
    int node = blockIdx.x * 4 + nl;     // NN % 4 == 0
    int b = node * CAP;
    int deg = g_wp[node];

    float4 edv = *reinterpret_cast<const float4*>(&ed[node * H1]);

    // ---- phase A: one slot per lane ----
    int slot = half * 32 + lane;
    float4 p = make_float4(0,0,0,0);
    if (slot < deg) {
        int sn = g_src[b + slot];
        s_sn[nl][slot] = sn;
        float4 ev = *reinterpret_cast<const float4*>(&es[sn * H1]);
        p.x = __expf(lrelu(ev.x + edv.x)); p.y = __expf(lrelu(ev.y + edv.y));
        p.z = __expf(lrelu(ev.z + edv.z)); p.w = __expf(lrelu(ev.w + edv.w));
        *reinterpret_cast<float4*>(&s_p[nl][slot][0]) = p;
    }
    float4 ps = p;
    #pragma unroll
    for (int off = 16; off; off >>= 1) {
        ps.x += __shfl_xor_sync(0xffffffffu, ps.x, off);
        ps.y += __shfl_xor_sync(0xffffffffu, ps.y, off);
        ps.z += __shfl_xor_sync(0xffffffffu, ps.z, off);
        ps.w += __shfl_xor_sync(0xffffffffu, ps.w, off);
    }
    if (lane == 0)
        *reinterpret_cast<float4*>(&s_sum[nl][half][0]) = ps;
    __syncthreads();

    int head = lane >> 3;
    float sumh = s_sum[nl][0][head] + s_sum[nl][1][head];
    float invh = 1.f / (sumh + 1e-16f);

    // ---- phase B: interleaved edges (this warp: half, half+2, ...) ----
    float4 a0 = make_float4(0,0,0,0), a1 = make_float4(0,0,0,0);
    int s = half;
    for (; s + 2 < deg; s += 4) {   // 2-edge pipeline: s, s+2
        int sa = s_sn[nl][s];
        int sb = s_sn[nl][s + 2];
        float pa = s_p[nl][s][head];
        float pb = s_p[nl][s + 2][head];
        uint4 ra = *reinterpret_cast<const uint4*>(&g_h1h[(size_t)sa * F1 + lane * 8]);
        uint4 rb = *reinterpret_cast<const uint4*>(&g_h1h[(size_t)sb * F1 + lane * 8]);
        float2 a00 = __half22float2(*reinterpret_cast<__half2*>(&ra.x));
        float2 a01 = __half22float2(*reinterpret_cast<__half2*>(&ra.y));
        float2 a02 = __half22float2(*reinterpret_cast<__half2*>(&ra.z));
        float2 a03 = __half22float2(*reinterpret_cast<__half2*>(&ra.w));
        float2 b00 = __half22float2(*reinterpret_cast<__half2*>(&rb.x));
        float2 b01 = __half22float2(*reinterpret_cast<__half2*>(&rb.y));
        float2 b02 = __half22float2(*reinterpret_cast<__half2*>(&rb.z));
        float2 b03 = __half22float2(*reinterpret_cast<__half2*>(&rb.w));
        a0.x += pa * a00.x + pb * b00.x; a0.y += pa * a00.y + pb * b00.y;
        a0.z += pa * a01.x + pb * b01.x; a0.w += pa * a01.y + pb * b01.y;
        a1.x += pa * a02.x + pb * b02.x; a1.y += pa * a02.y + pb * b02.y;
        a1.z += pa * a03.x + pb * b03.x; a1.w += pa * a03.y + pb * b03.y;
    }
    for (; s < deg; s += 2) {
        int sn = s_sn[nl][s];
        float pp = s_p[nl][s][head];
        uint4 raw = *reinterpret_cast<const uint4*>(&g_h1h[(size_t)sn * F1 + lane * 8]);
        float2 v0 = __half22float2(*reinterpret_cast<__half2*>(&raw.x));
        float2 v1 = __half22float2(*reinterpret_cast<__half2*>(&raw.y));
        float2 v2 = __half22float2(*reinterpret_cast<__half2*>(&raw.z));
        float2 v3 = __half22float2(*reinterpret_cast<__half2*>(&raw.w));
        a0.x += pp * v0.x; a0.y += pp * v0.y; a0.z += pp * v1.x; a0.w += pp * v1.y;
        a1.x += pp * v2.x; a1.y += pp * v2.y; a1.z += pp * v3.x; a1.w += pp * v3.y;
    }

    // ---- combine: warp1 stores its accum, warp0 adds + finishes ----
    if (half == 1) {
        s_acc[nl][0][lane] = a0.x; s_acc[nl][1][lane] = a0.y;
        s_acc[nl][2][lane] = a0.z; s_acc[nl][3][lane] = a0.w;
        s_acc[nl][4][lane] = a1.x; s_acc[nl][5][lane] = a1.y;
        s_acc[nl][6][lane] = a1.z; s_acc[nl][7][lane] = a1.w;
    }
    __syncthreads();
    if (half == 0) {
        a0.x += s_acc[nl][0][lane]; a0.y += s_acc[nl][1][lane];
        a0.z += s_acc[nl][2][lane]; a0.w += s_acc[nl][3][lane];
        a1.x += s_acc[nl][4][lane]; a1.y += s_acc[nl][5][lane];
        a1.z += s_acc[nl][6][lane]; a1.w += s_acc[nl][7][lane];

        int c0 = lane * 8;
        float4 bb0 = *reinterpret_cast<const float4*>(&b1[c0]);
        float4 bb1 = *reinterpret_cast<const float4*>(&b1[c0 + 4]);
        __half2 o0 = __floats2half2_rn(elu(a0.x * invh + bb0.x), elu(a0.y * invh + bb0.y));
        __half2 o1 = __floats2half2_rn(elu(a0.z * invh + bb0.z), elu(a0.w * invh + bb0.w));
        __half2 o2 = __floats2half2_rn(elu(a1.x * invh + bb1.x), elu(a1.y * invh + bb1.y));
        __half2 o3 = __floats2half2_rn(elu(a1.z * invh + bb1.z), elu(a1.w * invh + bb1.w));
        uint4 packed = make_uint4(*reinterpret_cast<unsigned*>(&o0),
                                  *reinterpret_cast<unsigned*>(&o1),
                                  *reinterpret_cast<unsigned*>(&o2),
                                  *reinterpret_cast<unsigned*>(&o3));
        *reinterpret_cast<uint4*>(&g_o1h[(size_t)node * F1 + c0]) = packed;
    }
}

// ---------------- layer-2 aggregation: 8 lanes per node (R12 form) ----------------
__global__ __launch_bounds__(256) void agg2_fused(
        const float* __restrict__ es,
        const float* __restrict__ ed,
        const float* __restrict__ b2,
        const float* __restrict__ Wo,
        const float* __restrict__ bo,
        float* __restrict__ out) {
    __shared__ int   s_src[8][4][64];
    __shared__ float s_p[8][4][64];
    int tid = threadIdx.x;
    int wid = tid >> 5;
    int lane = tid & 31;
    int grp = lane >> 3;          // node within warp (0..3)
    int gl = lane & 7;            // lane within 8-lane group
    int node = blockIdx.x * 32 + wid * 4 + grp;
    if (node >= NN) return;
    int b = node * CAP;
    int deg = g_wp[node];

    float edv = ed[node];

    // ---- phase A ----
    float mx = -1e30f;
    #pragma unroll
    for (int k = 0; k < 8; k++) {
        int idx = gl + k * 8;
        if (idx < deg) {
            int sn = g_src[b + idx];
            float l = lrelu(es[sn] + edv);
            s_src[wid][grp][idx] = sn;
            s_p[wid][grp][idx] = l;
            mx = fmaxf(mx, l);
        }
    }
    #pragma unroll
    for (int off = 4; off; off >>= 1)
        mx = fmaxf(mx, __shfl_xor_sync(0xffffffffu, mx, off, 8));
    float psum = 0.f;
    float pk[8];
    #pragma unroll
    for (int k = 0; k < 8; k++) {
        int idx = gl + k * 8;
        if (idx < deg) {
            pk[k] = __expf(s_p[wid][grp][idx] - mx);
            psum += pk[k];
        }
    }
    #pragma unroll
    for (int off = 4; off; off >>= 1)
        psum += __shfl_xor_sync(0xffffffffu, psum, off, 8);
    float inv = 1.f / (psum + 1e-16f);
    #pragma unroll
    for (int k = 0; k < 8; k++) {
        int idx = gl + k * 8;
        if (idx < deg) s_p[wid][grp][idx] = pk[k] * inv;
    }
    __syncwarp();

    // ---- phase B: 8 channels per lane ----
    int c0 = gl * 8;
    float4 aa = make_float4(0,0,0,0), ab = make_float4(0,0,0,0);
    for (int s = 0; s < deg; s++) {
        int sn = s_src[wid][grp][s];
        float p = s_p[wid][grp][s];
        uint4 raw = *reinterpret_cast<const uint4*>(&g_h2h[(size_t)sn * C2 + c0]);
        float2 v0 = __half22float2(*reinterpret_cast<__half2*>(&raw.x));
        float2 v1 = __half22float2(*reinterpret_cast<__half2*>(&raw.y));
        float2 v2 = __half22float2(*reinterpret_cast<__half2*>(&raw.z));
        float2 v3 = __half22float2(*reinterpret_cast<__half2*>(&raw.w));
        aa.x += p * v0.x; aa.y += p * v0.y; aa.z += p * v1.x; aa.w += p * v1.y;
        ab.x += p * v2.x; ab.y += p * v2.y; ab.z += p * v3.x; ab.w += p * v3.y;
    }

    float4 b20 = *reinterpret_cast<const float4*>(&b2[c0]);
    float4 b21 = *reinterpret_cast<const float4*>(&b2[c0 + 4]);
    float4 w0  = *reinterpret_cast<const float4*>(&Wo[c0]);
    float4 w1  = *reinterpret_cast<const float4*>(&Wo[c0 + 4]);
    float partial =
        elu(aa.x + b20.x) * w0.x + elu(aa.y + b20.y) * w0.y +
        elu(aa.z + b20.z) * w0.z + elu(aa.w + b20.w) * w0.w +
        elu(ab.x + b21.x) * w1.x + elu(ab.y + b21.y) * w1.y +
        elu(ab.z + b21.z) * w1.z + elu(ab.w + b21.w) * w1.w;
    #pragma unroll
    for (int off = 4; off; off >>= 1)
        partial += __shfl_xor_sync(0xffffffffu, partial, off, 8);
    if (gl == 0) {
        out[node] = partial + bo[0];
        g_wp[node] = 0;   // reset for next graph replay
    }
}

// ---------------- launch ----------------
extern "C" void kernel_launch(void* const* d_in, const int* in_sizes, int n_in,
                              void* d_out, int out_size) {
    const float* x      = (const float*)d_in[0];
    const float* W1     = (const float*)d_in[1];
    const float* a_src1 = (const float*)d_in[2];
    const float* a_dst1 = (const float*)d_in[3];
    const float* b1     = (const float*)d_in[4];
    const float* W2     = (const float*)d_in[5];
    const float* a_src2 = (const float*)d_in[6];
    const float* a_dst2 = (const float*)d_in[7];
    const float* b2     = (const float*)d_in[8];
    const float* Wo     = (const float*)d_in[9];
    const float* bo     = (const float*)d_in[10];
    const int* edge_index = (const int*)d_in[11];
    float* out = (float*)d_out;

    __half *h1h, *h2h, *o1h;
    float *es1, *ed1, *es2, *ed2;
    cudaGetSymbolAddress((void**)&h1h, g_h1h);
    cudaGetSymbolAddress((void**)&h2h, g_h2h);
    cudaGetSymbolAddress((void**)&o1h, g_o1h);
    cudaGetSymbolAddress((void**)&es1, g_es1);
    cudaGetSymbolAddress((void**)&ed1, g_ed1);
    cudaGetSymbolAddress((void**)&es2, g_es2);
    cudaGetSymbolAddress((void**)&ed2, g_ed2);

    // 1) edge bucketing (first blocks) overlapped with wide GEMM1 (+ es/ed epilogue)
    gemm1_plus_bucket<<<GEMM1_BLOCKS + BUCKET_BLOCKS, 256>>>(
        x, W1, a_src1, a_dst1, h1h, es1, ed1, edge_index);

    // 2) fused softmax + aggregation layer 1 (2 warps/node, edge-interleaved)
    agg1_fused<<<NN / 4, 256>>>(es1, ed1, b1);

    // 3) layer 2 GEMM (fp16 A, prefetch) + es/ed epilogue
    gemm2_kernel<<<GEMM1_MBLK, 256>>>(o1h, W2, a_src2, a_dst2, h2h, es2, ed2);

    // 4) fused softmax + aggregation layer 2 + projection (+ wp reset)
    agg2_fused<<<(NN + 31) / 32, 256>>>(es2, ed2, b2, Wo, bo, out);
}

// round 17
// speedup vs baseline: 1.1145x; 1.1145x over previous
#include <cuda_runtime.h>
#include <cuda_fp16.h>
#include <math.h>

// ---------------- problem constants ----------------
#define NN     50000
#define EE     800000
#define ET     850000      // EE + NN self loops
#define INCH   128
#define H1     4
#define C1     64
#define F1     256         // H1*C1
#define C2     64
#define CAP    64          // bucket capacity per node (P(deg+1 > 64) ~ 1e-20)

#define GEMM1_MBLK  ((NN + 127) / 128)       // 391
#define GEMM1_BLOCKS (GEMM1_MBLK * 2)        // 782 (2 head-pairs)
#define BUCKET_BLOCKS 832

// ---------------- device scratch ----------------
__device__ __half g_h1h[NN * F1];     // x @ W1 (fp16)
__device__ __half g_o1h[NN * F1];     // elu(layer1 out + b1) fp16 (GEMM2 input)
__device__ __half g_h2h[NN * C2];     // o1 @ W2 (fp16)
__device__ float  g_es1[NN * H1];
__device__ float  g_ed1[NN * H1];
__device__ float  g_es2[NN];
__device__ float  g_ed2[NN];
__device__ int    g_wp[NN];           // per-node incoming count (zeroed at start, re-zeroed at end)
__device__ int    g_src[NN * CAP];    // bucketed source nodes per dst

// ---------------- helpers ----------------
__device__ __forceinline__ float elu(float x) {
    return x > 0.f ? x : (expf(x) - 1.f);
}
__device__ __forceinline__ float lrelu(float x) {
    return fmaxf(x, 0.2f * x);
}
// fp16 m16n8k16 MMA, fp32 accumulate
__device__ __forceinline__ void mma_f16(float* d, const unsigned* a, const unsigned* b) {
    asm volatile(
        "mma.sync.aligned.m16n8k16.row.col.f32.f16.f16.f32 "
        "{%0,%1,%2,%3}, {%4,%5,%6,%7}, {%8,%9}, {%0,%1,%2,%3};"
        : "+f"(d[0]), "+f"(d[1]), "+f"(d[2]), "+f"(d[3])
        : "r"(a[0]), "r"(a[1]), "r"(a[2]), "r"(a[3]), "r"(b[0]), "r"(b[1]));
}

// ================= GEMM1 wide body: 128(M) x 128(N = 2 heads), fp16 split-A =================
// Double-buffered smem stages: 1 syncthreads per stage, STS(s+1) overlaps MMA(s).
__device__ void gemm1_body(
        const float* __restrict__ A, const float* __restrict__ B,
        const float* __restrict__ asrc, const float* __restrict__ adst,
        __half* __restrict__ hout,
        float* __restrict__ es, float* __restrict__ ed,
        int headpair, int by) {
    __shared__ unsigned Ash[2][2][128][12];   // [buf][hi/lo][m][kpair]
    __shared__ unsigned Bsh[2][8][136];       // [buf][kpair][n]
    __shared__ float s_as[128], s_ad[128];

    const int M = NN, N = F1, K = INCH, H = H1;
    int tid = threadIdx.x;
    int lane = tid & 31, wid = tid >> 5;
    int warp_m = wid >> 1, warp_n = wid & 1;
    int g = lane >> 2, t = lane & 3;
    int bm0 = by * 128, bn0 = headpair * 128;
    int head = headpair * 2 + warp_n;

    if (tid < 128) {
        s_as[tid] = asrc[bn0 + tid];
        s_ad[tid] = adst[bn0 + tid];
    }

    float acc[2][8][4];
    #pragma unroll
    for (int im = 0; im < 2; im++)
        #pragma unroll
        for (int in = 0; in < 8; in++)
            #pragma unroll
            for (int c = 0; c < 4; c++) acc[im][in][c] = 0.f;

    int arow = tid >> 1;
    int acb  = (tid & 1) * 8;
    int apb  = (tid & 1) * 4;
    bool arow_ok = (bm0 + arow) < M;
    const float* aptrf = A + (size_t)(bm0 + arow) * K + acb;
    int brp = tid >> 5;
    int bnc = lane * 4;
    const float* bptr = B + (size_t)(2 * brp) * N + bn0 + bnc;

    float4 av0 = make_float4(0,0,0,0), av1 = av0, bve, bvo;
    if (arow_ok) {
        av0 = *reinterpret_cast<const float4*>(aptrf);
        av1 = *reinterpret_cast<const float4*>(aptrf + 4);
    }
    bve = *reinterpret_cast<const float4*>(bptr);
    bvo = *reinterpret_cast<const float4*>(bptr + N);

    auto stage_sts = [&](int buf) {
        float vv[8] = {av0.x, av0.y, av0.z, av0.w, av1.x, av1.y, av1.z, av1.w};
        __half h[8], l[8];
        #pragma unroll
        for (int j = 0; j < 8; j++) {
            h[j] = __float2half_rn(vv[j]);
            l[j] = __float2half_rn(vv[j] - __half2float(h[j]));
        }
        unsigned ph[4], pl[4];
        #pragma unroll
        for (int p = 0; p < 4; p++) {
            __half2 hh = __halves2half2(h[2*p], h[2*p+1]);
            __half2 ll = __halves2half2(l[2*p], l[2*p+1]);
            ph[p] = *reinterpret_cast<unsigned*>(&hh);
            pl[p] = *reinterpret_cast<unsigned*>(&ll);
        }
        *reinterpret_cast<uint4*>(&Ash[buf][0][arow][apb]) = make_uint4(ph[0],ph[1],ph[2],ph[3]);
        *reinterpret_cast<uint4*>(&Ash[buf][1][arow][apb]) = make_uint4(pl[0],pl[1],pl[2],pl[3]);

        __half2 p0 = __halves2half2(__float2half_rn(bve.x), __float2half_rn(bvo.x));
        __half2 p1 = __halves2half2(__float2half_rn(bve.y), __float2half_rn(bvo.y));
        __half2 p2 = __halves2half2(__float2half_rn(bve.z), __float2half_rn(bvo.z));
        __half2 p3 = __halves2half2(__float2half_rn(bve.w), __float2half_rn(bvo.w));
        *reinterpret_cast<uint4*>(&Bsh[buf][brp][bnc]) = make_uint4(
            *reinterpret_cast<unsigned*>(&p0), *reinterpret_cast<unsigned*>(&p1),
            *reinterpret_cast<unsigned*>(&p2), *reinterpret_cast<unsigned*>(&p3));
    };

    stage_sts(0);
    __syncthreads();

    const int S = K / 16;   // 8 stages
    for (int s = 0; s < S; s++) {
        int buf = s & 1;
        int kn = (s + 1) * 16;
        if (kn < K) {
            if (arow_ok) {
                av0 = *reinterpret_cast<const float4*>(aptrf + kn);
                av1 = *reinterpret_cast<const float4*>(aptrf + kn + 4);
            }
            bve = *reinterpret_cast<const float4*>(bptr + (size_t)kn * N);
            bvo = *reinterpret_cast<const float4*>(bptr + (size_t)(kn + 1) * N);
        }

        {
            unsigned ah[2][4], al[2][4], bf[8][2];
            #pragma unroll
            for (int im = 0; im < 2; im++) {
                int mr = warp_m * 32 + im * 16 + g;
                ah[im][0] = Ash[buf][0][mr][t];
                ah[im][1] = Ash[buf][0][mr + 8][t];
                ah[im][2] = Ash[buf][0][mr][t + 4];
                ah[im][3] = Ash[buf][0][mr + 8][t + 4];
                al[im][0] = Ash[buf][1][mr][t];
                al[im][1] = Ash[buf][1][mr + 8][t];
                al[im][2] = Ash[buf][1][mr][t + 4];
                al[im][3] = Ash[buf][1][mr + 8][t + 4];
            }
            #pragma unroll
            for (int in = 0; in < 8; in++) {
                int nc = warp_n * 64 + in * 8 + g;
                bf[in][0] = Bsh[buf][t][nc];
                bf[in][1] = Bsh[buf][t + 4][nc];
            }
            #pragma unroll
            for (int im = 0; im < 2; im++)
                #pragma unroll
                for (int in = 0; in < 8; in++) {
                    mma_f16(acc[im][in], ah[im], bf[in]);
                    mma_f16(acc[im][in], al[im], bf[in]);
                }
        }

        if (kn < K) stage_sts(buf ^ 1);
        __syncthreads();
    }

    #pragma unroll
    for (int im = 0; im < 2; im++) {
        #pragma unroll
        for (int hh = 0; hh < 2; hh++) {
            int row = bm0 + warp_m * 32 + im * 16 + hh * 8 + g;
            float pe = 0.f, pd = 0.f;
            #pragma unroll
            for (int in = 0; in < 8; in++) {
                int c = warp_n * 64 + in * 8 + 2 * t;
                float v0 = acc[im][in][2 * hh];
                float v1 = acc[im][in][2 * hh + 1];
                pe += v0 * s_as[c] + v1 * s_as[c + 1];
                pd += v0 * s_ad[c] + v1 * s_ad[c + 1];
                if (row < M) {
                    __half2 p = __floats2half2_rn(v0, v1);
                    *reinterpret_cast<__half2*>(&hout[(size_t)row * N + bn0 + c]) = p;
                }
            }
            pe += __shfl_down_sync(0xffffffffu, pe, 1, 4);
            pe += __shfl_down_sync(0xffffffffu, pe, 2, 4);
            pd += __shfl_down_sync(0xffffffffu, pd, 1, 4);
            pd += __shfl_down_sync(0xffffffffu, pd, 2, 4);
            if (t == 0 && row < M) {
                es[row * H + head] = pe;
                ed[row * H + head] = pd;
            }
        }
    }
}

// ================= GEMM2 body: 128(M) x 64(N), fp16 A, prefetch =================
#define BKT 16
__device__ void gemm2_body(
        const __half* __restrict__ A, const float* __restrict__ B,
        const float* __restrict__ asrc, const float* __restrict__ adst,
        __half* __restrict__ hout,
        float* __restrict__ es, float* __restrict__ ed,
        int by) {
    const int M = NN, N = C2, K = F1;
    __shared__ unsigned Ash[128][12];
    __shared__ unsigned Bsh[8][72];
    __shared__ float s_as[64], s_ad[64];
    __shared__ float s_esp[2][128], s_edp[2][128];

    int tid = threadIdx.x;
    int lane = tid & 31, wid = tid >> 5;
    int warp_m = wid >> 1, warp_n = wid & 1;
    int g = lane >> 2, t = lane & 3;
    int bm0 = by * 128;

    if (tid < 64) {
        s_as[tid] = asrc[tid];
        s_ad[tid] = adst[tid];
    }

    float acc[2][4][4];
    #pragma unroll
    for (int im = 0; im < 2; im++)
        #pragma unroll
        for (int in = 0; in < 4; in++)
            #pragma unroll
            for (int c = 0; c < 4; c++) acc[im][in][c] = 0.f;

    int arow = tid >> 1;
    int acb  = (tid & 1) * 8;
    int apb  = (tid & 1) * 4;
    bool arow_ok = (bm0 + arow) < M;
    const __half* aptrh = A + (size_t)(bm0 + arow) * K + acb;
    int brp = tid >> 4;
    int bnc = (tid & 15) * 4;
    const float* bptr = B + (size_t)(2 * brp) * N + bnc;
    bool bload = tid < 128;

    uint4 ar = make_uint4(0u,0u,0u,0u);
    float4 bve = make_float4(0,0,0,0), bvo = bve;
    if (arow_ok) ar = *reinterpret_cast<const uint4*>(aptrh);
    if (bload) {
        bve = *reinterpret_cast<const float4*>(bptr);
        bvo = *reinterpret_cast<const float4*>(bptr + N);
    }

    for (int k0 = 0; k0 < K; k0 += BKT) {
        *reinterpret_cast<uint4*>(&Ash[arow][apb]) = ar;
        if (bload) {
            __half2 p0 = __halves2half2(__float2half_rn(bve.x), __float2half_rn(bvo.x));
            __half2 p1 = __halves2half2(__float2half_rn(bve.y), __float2half_rn(bvo.y));
            __half2 p2 = __halves2half2(__float2half_rn(bve.z), __float2half_rn(bvo.z));
            __half2 p3 = __halves2half2(__float2half_rn(bve.w), __float2half_rn(bvo.w));
            *reinterpret_cast<uint4*>(&Bsh[brp][bnc]) = make_uint4(
                *reinterpret_cast<unsigned*>(&p0), *reinterpret_cast<unsigned*>(&p1),
                *reinterpret_cast<unsigned*>(&p2), *reinterpret_cast<unsigned*>(&p3));
        }
        __syncthreads();

        int kn = k0 + BKT;
        if (kn < K) {
            if (arow_ok) ar = *reinterpret_cast<const uint4*>(aptrh + kn);
            if (bload) {
                bve = *reinterpret_cast<const float4*>(bptr + (size_t)kn * N);
                bvo = *reinterpret_cast<const float4*>(bptr + (size_t)(kn + 1) * N);
            }
        }

        {
            unsigned ah[2][4], bf[4][2];
            #pragma unroll
            for (int im = 0; im < 2; im++) {
                int mr = warp_m * 32 + im * 16 + g;
                ah[im][0] = Ash[mr][t];
                ah[im][1] = Ash[mr + 8][t];
                ah[im][2] = Ash[mr][t + 4];
                ah[im][3] = Ash[mr + 8][t + 4];
            }
            #pragma unroll
            for (int in = 0; in < 4; in++) {
                int nc = warp_n * 32 + in * 8 + g;
                bf[in][0] = Bsh[t][nc];
                bf[in][1] = Bsh[t + 4][nc];
            }
            #pragma unroll
            for (int im = 0; im < 2; im++)
                #pragma unroll
                for (int in = 0; in < 4; in++)
                    mma_f16(acc[im][in], ah[im], bf[in]);
        }
        __syncthreads();
    }

    #pragma unroll
    for (int im = 0; im < 2; im++) {
        #pragma unroll
        for (int hh = 0; hh < 2; hh++) {
            int lr = warp_m * 32 + im * 16 + hh * 8 + g;
            int row = bm0 + lr;
            float pe = 0.f, pd = 0.f;
            #pragma unroll
            for (int in = 0; in < 4; in++) {
                int c = warp_n * 32 + in * 8 + 2 * t;
                float v0 = acc[im][in][2 * hh];
                float v1 = acc[im][in][2 * hh + 1];
                pe += v0 * s_as[c] + v1 * s_as[c + 1];
                pd += v0 * s_ad[c] + v1 * s_ad[c + 1];
                if (row < M) {
                    __half2 p = __floats2half2_rn(v0, v1);
                    *reinterpret_cast<__half2*>(&hout[(size_t)row * N + c]) = p;
                }
            }
            pe += __shfl_down_sync(0xffffffffu, pe, 1, 4);
            pe += __shfl_down_sync(0xffffffffu, pe, 2, 4);
            pd += __shfl_down_sync(0xffffffffu, pd, 1, 4);
            pd += __shfl_down_sync(0xffffffffu, pd, 2, 4);
            if (t == 0) {
                s_esp[warp_n][lr] = pe;
                s_edp[warp_n][lr] = pd;
            }
        }
    }
    __syncthreads();
    if (tid < 128) {
        int row = bm0 + tid;
        if (row < M) {
            es[row] = s_esp[0][tid] + s_esp[1][tid];
            ed[row] = s_edp[0][tid] + s_edp[1][tid];
        }
    }
}

// ---------------- combined kernel: edge-bucket blocks FIRST, then GEMM1 blocks ----------------
__global__ __launch_bounds__(256) void gemm1_plus_bucket(
        const float* __restrict__ A, const float* __restrict__ B,
        const float* __restrict__ asrc, const float* __restrict__ adst,
        __half* __restrict__ hout,
        float* __restrict__ es, float* __restrict__ ed,
        const int* __restrict__ edge_index) {
    int bx = blockIdx.x;
    if (bx < BUCKET_BLOCKS) {
        const int* srcp = edge_index;
        const int* dstp = edge_index + EE;
        int i = bx * 256 + threadIdx.x;
        int stride = BUCKET_BLOCKS * 256;
        for (int e = i; e < ET; e += stride) {
            int s, d;
            if (e < EE) { s = srcp[e]; d = dstp[e]; }
            else { s = e - EE; d = s; }
            int slot = atomicAdd(&g_wp[d], 1);
            g_src[d * CAP + slot] = s;
        }
    } else {
        int gb = bx - BUCKET_BLOCKS;
        gemm1_body(A, B, asrc, adst, hout, es, ed, gb & 1, gb >> 1);
    }
}

// ---------------- GEMM2 kernel ----------------
__global__ __launch_bounds__(256) void gemm2_kernel(
        const __half* __restrict__ A, const float* __restrict__ B,
        const float* __restrict__ asrc, const float* __restrict__ adst,
        __half* __restrict__ hout,
        float* __restrict__ es, float* __restrict__ ed) {
    gemm2_body(A, B, asrc, adst, hout, es, ed, blockIdx.x);
}

// ---------------- layer-1 aggregation: 1 warp/node, unnormalized-p softmax ----------------
__global__ __launch_bounds__(256) void agg1_fused(
        const float* __restrict__ es,
        const float* __restrict__ ed,
        const float* __restrict__ b1) {
    __shared__ float s_p[8][64][H1];   // UNNORMALIZED p, [warp][slot][head]
    int w = threadIdx.x >> 5;
    int gid = blockIdx.x * blockDim.x + threadIdx.x;
    int node = gid >> 5;
    int lane = gid & 31;
    if (node >= NN) return;
    int b = node * CAP;
    int deg = g_wp[node];
    bool h0 = lane < deg, hx1 = lane + 32 < deg;

    float4 edv = *reinterpret_cast<const float4*>(&ed[node * H1]);

    // ---- phase A: p = exp(leaky(es+ed)), stash raw p, reduce sum ----
    int sn0 = 0, sn1 = 0;
    float4 p0 = make_float4(0,0,0,0), p1 = make_float4(0,0,0,0);
    float4 ps = make_float4(0,0,0,0);
    if (h0) {
        sn0 = g_src[b + lane];
        float4 ev = *reinterpret_cast<const float4*>(&es[sn0 * H1]);
        p0.x = __expf(lrelu(ev.x + edv.x)); p0.y = __expf(lrelu(ev.y + edv.y));
        p0.z = __expf(lrelu(ev.z + edv.z)); p0.w = __expf(lrelu(ev.w + edv.w));
        ps = p0;
        *reinterpret_cast<float4*>(&s_p[w][lane][0]) = p0;
    }
    if (hx1) {
        sn1 = g_src[b + lane + 32];
        float4 ev = *reinterpret_cast<const float4*>(&es[sn1 * H1]);
        p1.x = __expf(lrelu(ev.x + edv.x)); p1.y = __expf(lrelu(ev.y + edv.y));
        p1.z = __expf(lrelu(ev.z + edv.z)); p1.w = __expf(lrelu(ev.w + edv.w));
        ps.x += p1.x; ps.y += p1.y; ps.z += p1.z; ps.w += p1.w;
        *reinterpret_cast<float4*>(&s_p[w][lane + 32][0]) = p1;
    }
    #pragma unroll
    for (int off = 16; off; off >>= 1) {
        ps.x += __shfl_xor_sync(0xffffffffu, ps.x, off);
        ps.y += __shfl_xor_sync(0xffffffffu, ps.y, off);
        ps.z += __shfl_xor_sync(0xffffffffu, ps.z, off);
        ps.w += __shfl_xor_sync(0xffffffffu, ps.w, off);
    }
    int head = lane >> 3;
    float psh = (head == 0) ? ps.x : (head == 1) ? ps.y : (head == 2) ? ps.z : ps.w;
    float invh = 1.f / (psh + 1e-16f);
    __syncwarp();

    // ---- phase B: channel-parallel weighted accumulation, 4-edge pipeline ----
    float4 a0 = make_float4(0,0,0,0), a1 = make_float4(0,0,0,0);
    int n1 = deg < 32 ? deg : 32;
    int s = 0;
    for (; s + 3 < n1; s += 4) {
        int sa = __shfl_sync(0xffffffffu, sn0, s);
        int sb = __shfl_sync(0xffffffffu, sn0, s + 1);
        int sc = __shfl_sync(0xffffffffu, sn0, s + 2);
        int sd = __shfl_sync(0xffffffffu, sn0, s + 3);
        float pa = s_p[w][s][head];
        float pb = s_p[w][s + 1][head];
        float pc = s_p[w][s + 2][head];
        float pd = s_p[w][s + 3][head];
        uint4 ra = *reinterpret_cast<const uint4*>(&g_h1h[(size_t)sa * F1 + lane * 8]);
        uint4 rb = *reinterpret_cast<const uint4*>(&g_h1h[(size_t)sb * F1 + lane * 8]);
        uint4 rc = *reinterpret_cast<const uint4*>(&g_h1h[(size_t)sc * F1 + lane * 8]);
        uint4 rd = *reinterpret_cast<const uint4*>(&g_h1h[(size_t)sd * F1 + lane * 8]);
        #pragma unroll
        for (int q = 0; q < 4; q++) {
            uint4 r = (q == 0) ? ra : (q == 1) ? rb : (q == 2) ? rc : rd;
            float p = (q == 0) ? pa : (q == 1) ? pb : (q == 2) ? pc : pd;
            float2 v0 = __half22float2(*reinterpret_cast<__half2*>(&r.x));
            float2 v1 = __half22float2(*reinterpret_cast<__half2*>(&r.y));
            float2 v2 = __half22float2(*reinterpret_cast<__half2*>(&r.z));
            float2 v3 = __half22float2(*reinterpret_cast<__half2*>(&r.w));
            a0.x += p * v0.x; a0.y += p * v0.y; a0.z += p * v1.x; a0.w += p * v1.y;
            a1.x += p * v2.x; a1.y += p * v2.y; a1.z += p * v3.x; a1.w += p * v3.y;
        }
    }
    for (; s < n1; s++) {
        int sn = __shfl_sync(0xffffffffu, sn0, s);
        float p = s_p[w][s][head];
        uint4 raw = *reinterpret_cast<const uint4*>(&g_h1h[(size_t)sn * F1 + lane * 8]);
        float2 v0 = __half22float2(*reinterpret_cast<__half2*>(&raw.x));
        float2 v1 = __half22float2(*reinterpret_cast<__half2*>(&raw.y));
        float2 v2 = __half22float2(*reinterpret_cast<__half2*>(&raw.z));
        float2 v3 = __half22float2(*reinterpret_cast<__half2*>(&raw.w));
        a0.x += p * v0.x; a0.y += p * v0.y; a0.z += p * v1.x; a0.w += p * v1.y;
        a1.x += p * v2.x; a1.y += p * v2.y; a1.z += p * v3.x; a1.w += p * v3.y;
    }
    for (s = 32; s < deg; s++) {
        int sn = __shfl_sync(0xffffffffu, sn1, s - 32);
        float p = s_p[w][s][head];
        uint4 raw = *reinterpret_cast<const uint4*>(&g_h1h[(size_t)sn * F1 + lane * 8]);
        float2 v0 = __half22float2(*reinterpret_cast<__half2*>(&raw.x));
        float2 v1 = __half22float2(*reinterpret_cast<__half2*>(&raw.y));
        float2 v2 = __half22float2(*reinterpret_cast<__half2*>(&raw.z));
        float2 v3 = __half22float2(*reinterpret_cast<__half2*>(&raw.w));
        a0.x += p * v0.x; a0.y += p * v0.y; a0.z += p * v1.x; a0.w += p * v1.y;
        a1.x += p * v2.x; a1.y += p * v2.y; a1.z += p * v3.x; a1.w += p * v3.y;
    }

    int c0 = lane * 8;
    float4 bb0 = *reinterpret_cast<const float4*>(&b1[c0]);
    float4 bb1 = *reinterpret_cast<const float4*>(&b1[c0 + 4]);
    __half2 o0 = __floats2half2_rn(elu(a0.x * invh + bb0.x), elu(a0.y * invh + bb0.y));
    __half2 o1 = __floats2half2_rn(elu(a0.z * invh + bb0.z), elu(a0.w * invh + bb0.w));
    __half2 o2 = __floats2half2_rn(elu(a1.x * invh + bb1.x), elu(a1.y * invh + bb1.y));
    __half2 o3 = __floats2half2_rn(elu(a1.z * invh + bb1.z), elu(a1.w * invh + bb1.w));
    uint4 packed = make_uint4(*reinterpret_cast<unsigned*>(&o0),
                              *reinterpret_cast<unsigned*>(&o1),
                              *reinterpret_cast<unsigned*>(&o2),
                              *reinterpret_cast<unsigned*>(&o3));
    *reinterpret_cast<uint4*>(&g_o1h[(size_t)node * F1 + c0]) = packed;
}

// ---------------- layer-2 aggregation: 8 lanes per node (R12 form) ----------------
__global__ __launch_bounds__(256) void agg2_fused(
        const float* __restrict__ es,
        const float* __restrict__ ed,
        const float* __restrict__ b2,
        const float* __restrict__ Wo,
        const float* __restrict__ bo,
        float* __restrict__ out) {
    __shared__ int   s_src[8][4][64];
    __shared__ float s_p[8][4][64];
    int tid = threadIdx.x;
    int wid = tid >> 5;
    int lane = tid & 31;
    int grp = lane >> 3;          // node within warp (0..3)
    int gl = lane & 7;            // lane within 8-lane group
    int node = blockIdx.x * 32 + wid * 4 + grp;
    if (node >= NN) return;
    int b = node * CAP;
    int deg = g_wp[node];

    float edv = ed[node];

    // ---- phase A ----
    float mx = -1e30f;
    #pragma unroll
    for (int k = 0; k < 8; k++) {
        int idx = gl + k * 8;
        if (idx < deg) {
            int sn = g_src[b + idx];
            float l = lrelu(es[sn] + edv);
            s_src[wid][grp][idx] = sn;
            s_p[wid][grp][idx] = l;
            mx = fmaxf(mx, l);
        }
    }
    #pragma unroll
    for (int off = 4; off; off >>= 1)
        mx = fmaxf(mx, __shfl_xor_sync(0xffffffffu, mx, off, 8));
    float psum = 0.f;
    float pk[8];
    #pragma unroll
    for (int k = 0; k < 8; k++) {
        int idx = gl + k * 8;
        if (idx < deg) {
            pk[k] = __expf(s_p[wid][grp][idx] - mx);
            psum += pk[k];
        }
    }
    #pragma unroll
    for (int off = 4; off; off >>= 1)
        psum += __shfl_xor_sync(0xffffffffu, psum, off, 8);
    float inv = 1.f / (psum + 1e-16f);
    #pragma unroll
    for (int k = 0; k < 8; k++) {
        int idx = gl + k * 8;
        if (idx < deg) s_p[wid][grp][idx] = pk[k] * inv;
    }
    __syncwarp();

    // ---- phase B: 8 channels per lane ----
    int c0 = gl * 8;
    float4 aa = make_float4(0,0,0,0), ab = make_float4(0,0,0,0);
    for (int s = 0; s < deg; s++) {
        int sn = s_src[wid][grp][s];
        float p = s_p[wid][grp][s];
        uint4 raw = *reinterpret_cast<const uint4*>(&g_h2h[(size_t)sn * C2 + c0]);
        float2 v0 = __half22float2(*reinterpret_cast<__half2*>(&raw.x));
        float2 v1 = __half22float2(*reinterpret_cast<__half2*>(&raw.y));
        float2 v2 = __half22float2(*reinterpret_cast<__half2*>(&raw.z));
        float2 v3 = __half22float2(*reinterpret_cast<__half2*>(&raw.w));
        aa.x += p * v0.x; aa.y += p * v0.y; aa.z += p * v1.x; aa.w += p * v1.y;
        ab.x += p * v2.x; ab.y += p * v2.y; ab.z += p * v3.x; ab.w += p * v3.y;
    }

    float4 b20 = *reinterpret_cast<const float4*>(&b2[c0]);
    float4 b21 = *reinterpret_cast<const float4*>(&b2[c0 + 4]);
    float4 w0  = *reinterpret_cast<const float4*>(&Wo[c0]);
    float4 w1  = *reinterpret_cast<const float4*>(&Wo[c0 + 4]);
    float partial =
        elu(aa.x + b20.x) * w0.x + elu(aa.y + b20.y) * w0.y +
        elu(aa.z + b20.z) * w0.z + elu(aa.w + b20.w) * w0.w +
        elu(ab.x + b21.x) * w1.x + elu(ab.y + b21.y) * w1.y +
        elu(ab.z + b21.z) * w1.z + elu(ab.w + b21.w) * w1.w;
    #pragma unroll
    for (int off = 4; off; off >>= 1)
        partial += __shfl_xor_sync(0xffffffffu, partial, off, 8);
    if (gl == 0) {
        out[node] = partial + bo[0];
        g_wp[node] = 0;   // reset for next graph replay
    }
}

// ---------------- launch ----------------
extern "C" void kernel_launch(void* const* d_in, const int* in_sizes, int n_in,
                              void* d_out, int out_size) {
    const float* x      = (const float*)d_in[0];
    const float* W1     = (const float*)d_in[1];
    const float* a_src1 = (const float*)d_in[2];
    const float* a_dst1 = (const float*)d_in[3];
    const float* b1     = (const float*)d_in[4];
    const float* W2     = (const float*)d_in[5];
    const float* a_src2 = (const float*)d_in[6];
    const float* a_dst2 = (const float*)d_in[7];
    const float* b2     = (const float*)d_in[8];
    const float* Wo     = (const float*)d_in[9];
    const float* bo     = (const float*)d_in[10];
    const int* edge_index = (const int*)d_in[11];
    float* out = (float*)d_out;

    __half *h1h, *h2h, *o1h;
    float *es1, *ed1, *es2, *ed2;
    cudaGetSymbolAddress((void**)&h1h, g_h1h);
    cudaGetSymbolAddress((void**)&h2h, g_h2h);
    cudaGetSymbolAddress((void**)&o1h, g_o1h);
    cudaGetSymbolAddress((void**)&es1, g_es1);
    cudaGetSymbolAddress((void**)&ed1, g_ed1);
    cudaGetSymbolAddress((void**)&es2, g_es2);
    cudaGetSymbolAddress((void**)&ed2, g_ed2);

    // 1) edge bucketing (first blocks) overlapped with wide GEMM1 (+ es/ed epilogue)
    gemm1_plus_bucket<<<GEMM1_BLOCKS + BUCKET_BLOCKS, 256>>>(
        x, W1, a_src1, a_dst1, h1h, es1, ed1, edge_index);

    // 2) fused softmax + aggregation layer 1 (1 warp/node, best measured form)
    agg1_fused<<<(NN * 32 + 255) / 256, 256>>>(es1, ed1, b1);

    // 3) layer 2 GEMM (fp16 A, prefetch) + es/ed epilogue
    gemm2_kernel<<<GEMM1_MBLK, 256>>>(o1h, W2, a_src2, a_dst2, h2h, es2, ed2);

    // 4) fused softmax + aggregation layer 2 (R12 form, best measured) + projection
    agg2_fused<<<(NN + 31) / 32, 256>>>(es2, ed2, b2, Wo, bo, out);
}